// round 13
// baseline (speedup 1.0000x reference)
#include <cuda_runtime.h>
#include <math.h>

#define NL 6
#define B  8
#define T  4
#define L  2048
#define H  16
#define D  64
#define E  1024
#define FF 4096
#define INDIM 32
#define NTOK 32
#define DEPTH 3

#define CACHE_F4 50331648LL            // NL*2*B*L*E/4

#define GDW() asm volatile("griddepcontrol.wait;" ::: "memory")

// -------- scratch (device globals) --------
__device__ __align__(16) float g_x    [NTOK * E];
__device__ __align__(16) float g_xn   [NTOK * E];
__device__ __align__(16) float g_q    [NTOK * E];
__device__ __align__(16) float g_seq  [NTOK * INDIM];
__device__ __align__(16) float g_part [524288];   // qkv (4x32x3072) / l1 (2x32x4096)
__device__ __align__(16) float g_part2[262144];   // op / l2 (8x32x1024)
__device__ __align__(16) float g_po   [B * H * 4 * T * D];
__device__ float g_m [B * H * 4 * T];
__device__ float g_l [B * H * 4 * T];

// -------- helpers --------
__device__ __forceinline__ void fma2(unsigned long long& d,
                                     unsigned long long a,
                                     unsigned long long b) {
    asm("fma.rn.f32x2 %0, %1, %2, %3;" : "=l"(d) : "l"(a), "l"(b), "l"(d));
}
__device__ __forceinline__ float2 upk(unsigned long long v) {
    float2 f;
    asm("mov.b64 {%0, %1}, %2;" : "=f"(f.x), "=f"(f.y) : "l"(v));
    return f;
}
__device__ __forceinline__ void cpa16(unsigned dst, const void* src) {
    asm volatile("cp.async.ca.shared.global [%0], [%1], 16;" :: "r"(dst), "l"(src));
}
#define CP_COMMIT() asm volatile("cp.async.commit_group;")
#define CP_WAIT1()  asm volatile("cp.async.wait_group 1;")
__device__ __forceinline__ float gelu1(float v) {
    return 0.5f * v * (1.0f + erff(v * 0.70710678118654752f));
}

// -------- bulk cache copy with NaN cleaning --------
__global__ void cache_copy_kernel(const float4* __restrict__ in,
                                  float4* __restrict__ out, long n)
{
    long i = (long)blockIdx.x * blockDim.x + threadIdx.x;
    if (i < n) {
        float4 v = in[i];
        v.x = isnan(v.x) ? 0.0f : v.x;
        v.y = isnan(v.y) ? 0.0f : v.y;
        v.z = isnan(v.z) ? 0.0f : v.z;
        v.w = isnan(v.w) ? 0.0f : v.w;
        out[i] = v;
    }
}

// -------- prep seq + new positions --------
__global__ void prep_pos_kernel(const float* __restrict__ seq,
                                const float* __restrict__ bos,
                                const int* __restrict__ positions,
                                float* __restrict__ out_seq,
                                float* __restrict__ out_pos)
{
    if (blockIdx.x < 4) {
        int i = blockIdx.x * 256 + threadIdx.x;
        float v = seq[i];
        out_seq[i] = isnan(v) ? bos[i & (INDIM - 1)] : v;
    } else {
        int i = threadIdx.x;
        if (i < NL * B) out_pos[i] = (float)(positions[i] + T);
    }
}

// ======== GEMM: Y[32,N] = Xeff[32,K] @ W[N,K]^T ========
// W: cp.async 3-stage pipeline, prefetched BEFORE the PDL wait.
// XMODE 0: X via cp.async (plain). XMODE 1: Xeff = gelu(part0+part1) computed
// in loader. XMODE 2: Xeff = softmax-combine of 4 attention chunk partials
// (X = po base; gm/gl aux). f32x2 compute.
template<int KSPLIT, int XMODE>
__global__ void gemv_kernel(const float* __restrict__ X,
                            const float* __restrict__ W,
                            float* __restrict__ Y,
                            float* __restrict__ part,
                            int K, int N,
                            const float* __restrict__ gm,
                            const float* __restrict__ gl)
{
    __shared__ __align__(16) float Xs[DEPTH][32][36];
    __shared__ __align__(16) float Ws[DEPTH][64][36];

    const int t    = threadIdx.x;
    const int lane = t & 31;
    const int c0   = (t >> 5) * 8;
    const int n0   = blockIdx.x * 64;
    const int Kc   = K / KSPLIT;
    const int kbase = blockIdx.y * Kc;
    const int nch  = Kc >> 5;

    const int xrow = t >> 3, xk4 = (t & 7) * 4;
    const int wrow = t >> 2, wk  = (t & 3) * 8;

    const float* xsrc = X + (size_t)xrow * K + kbase + xk4;
    const float* wsrc = W + (size_t)(n0 + wrow) * K + kbase + wk;

    const unsigned xbase = (unsigned)__cvta_generic_to_shared(&Xs[0][0][0])
                         + (unsigned)((xrow * 36 + xk4) * 4);
    const unsigned wbase = (unsigned)__cvta_generic_to_shared(&Ws[0][0][0])
                         + (unsigned)((wrow * 36 + wk) * 4);
    const unsigned XST = 32 * 36 * 4;
    const unsigned WST = 64 * 36 * 4;

    // ---- W prefetch stages 0..DEPTH-2 (launch-independent, pre-wait) ----
    #pragma unroll
    for (int p = 0; p < DEPTH - 1; p++) {
        if (p < nch) {
            cpa16(wbase + p * WST, wsrc + (size_t)p * 32);
            cpa16(wbase + p * WST + 16, wsrc + (size_t)p * 32 + 4);
        }
        if (XMODE != 0) CP_COMMIT();   // W-only groups
    }
    GDW();   // predecessor output now valid

    // X loader lambda (XMODE 1/2)
    auto loadX = [&](int ch) -> float4 {
        if (XMODE == 1) {
            const float* p0 = X + (size_t)xrow * K + kbase + ch * 32 + xk4;
            const float* p1 = p0 + (size_t)32 * K;
            float4 a = *(const float4*)p0;
            float4 b = *(const float4*)p1;
            float4 r;
            r.x = gelu1(a.x + b.x);
            r.y = gelu1(a.y + b.y);
            r.z = gelu1(a.z + b.z);
            r.w = gelu1(a.w + b.w);
            return r;
        } else {
            int f  = kbase + ch * 32 + xk4;
            int bb = xrow >> 2, tt = xrow & 3;
            int h  = f >> 6, d = f & 63;
            int bh = bb * 16 + h;
            int i0 = (bh * 4 + 0) * 4 + tt;
            int i1 = (bh * 4 + 1) * 4 + tt;
            int i2 = (bh * 4 + 2) * 4 + tt;
            int i3 = (bh * 4 + 3) * 4 + tt;
            float m0 = gm[i0], m1 = gm[i1], m2 = gm[i2], m3 = gm[i3];
            float M = fmaxf(fmaxf(m0, m1), fmaxf(m2, m3));
            float w0 = __expf(m0 - M), w1 = __expf(m1 - M);
            float w2 = __expf(m2 - M), w3 = __expf(m3 - M);
            float l = w0 * gl[i0] + w1 * gl[i1] + w2 * gl[i2] + w3 * gl[i3];
            const float4* po4 = (const float4*)X;
            float4 r0 = po4[(size_t)i0 * 16 + (d >> 2)];
            float4 r1 = po4[(size_t)i1 * 16 + (d >> 2)];
            float4 r2 = po4[(size_t)i2 * 16 + (d >> 2)];
            float4 r3 = po4[(size_t)i3 * 16 + (d >> 2)];
            float inv = 1.0f / l;
            float4 r;
            r.x = (w0 * r0.x + w1 * r1.x + w2 * r2.x + w3 * r3.x) * inv;
            r.y = (w0 * r0.y + w1 * r1.y + w2 * r2.y + w3 * r3.y) * inv;
            r.z = (w0 * r0.z + w1 * r1.z + w2 * r2.z + w3 * r3.z) * inv;
            r.w = (w0 * r0.w + w1 * r1.w + w2 * r2.w + w3 * r3.w) * inv;
            return r;
        }
    };

    float4 xcur = make_float4(0.f, 0.f, 0.f, 0.f);
    if (XMODE == 0) {
        if (0 < nch) cpa16(xbase, xsrc);
        CP_COMMIT();                       // group: {W0,W1,X0}
        if (1 < nch) cpa16(xbase + XST, xsrc + 32);
        CP_COMMIT();                       // group: {X1}
    } else {
        xcur = loadX(0);
    }

    unsigned long long acc[8];
    #pragma unroll
    for (int c = 0; c < 8; c++) acc[c] = 0ULL;

    int st = 0;
    int si = (DEPTH - 1) % DEPTH;
    for (int ch = 0; ch < nch; ch++) {
        CP_WAIT1();
        if (XMODE != 0)
            *(float4*)&Xs[st][xrow][xk4] = xcur;
        __syncthreads();

        float4 xnext;
        if (XMODE != 0 && ch + 1 < nch) xnext = loadX(ch + 1);

        #pragma unroll
        for (int p = 0; p < 16; p += 2) {
            unsigned long long x0 = *(const unsigned long long*)&Xs[st][lane][2 * p];
            unsigned long long x1 = *(const unsigned long long*)&Xs[st][lane][2 * p + 2];
            #pragma unroll
            for (int c = 0; c < 8; c++) {
                longlong2 w = *(const longlong2*)&Ws[st][c0 + c][2 * p];
                fma2(acc[c], x0, (unsigned long long)w.x);
                fma2(acc[c], x1, (unsigned long long)w.y);
            }
        }
        __syncthreads();

        int nc = ch + DEPTH - 1;
        if (nc < nch) {
            if (XMODE == 0)
                cpa16(xbase + si * XST, xsrc + (size_t)nc * 32);
            cpa16(wbase + si * WST, wsrc + (size_t)nc * 32);
            cpa16(wbase + si * WST + 16, wsrc + (size_t)nc * 32 + 4);
        }
        CP_COMMIT();
        st = (st == DEPTH - 1) ? 0 : st + 1;
        si = (si == DEPTH - 1) ? 0 : si + 1;
        if (XMODE != 0) xcur = xnext;
    }

    if (KSPLIT == 1) {
        #pragma unroll
        for (int c = 0; c < 8; c++) {
            float2 p = upk(acc[c]);
            Y[(size_t)lane * N + n0 + c0 + c] = p.x + p.y;
        }
    } else {
        float* pp = part + ((size_t)blockIdx.y * 32 + lane) * N + n0 + c0;
        #pragma unroll
        for (int c = 0; c < 8; c++) {
            float2 p = upk(acc[c]);
            pp[c] = p.x + p.y;
        }
    }
}

// -------- fused qkv split-K(4) reduce + RoPE + cache scatter --------
__global__ void reduce_rope_kernel(const float* __restrict__ part,
                                   const int* __restrict__ pos_l,
                                   float* __restrict__ qout,
                                   float* __restrict__ kcache,
                                   float* __restrict__ vcache)
{
    int id = blockIdx.x * 256 + threadIdx.x;  // 49152 pairs
    int tok = id / 1536;
    int f   = (id - tok * 1536) * 2;
    int b = tok >> 2, t = tok & 3;
    int pos = pos_l[b];
    GDW();
    float s0 = 0.f, s1 = 0.f;
    #pragma unroll
    for (int k = 0; k < 4; k++) {
        const float* p = part + ((size_t)(k * 32 + tok) * 3072) + f;
        s0 += p[0];
        s1 += p[1];
    }
    if (f < E) {
        int j = (f & 63) >> 1;
        float freq = __expf(-(float)j * (logf(10000.0f) / 32.0f));
        float sn, cs;
        sincosf((float)(pos + t) * freq, &sn, &cs);
        qout[(size_t)tok * E + f]     = s0 * cs - s1 * sn;
        qout[(size_t)tok * E + f + 1] = s0 * sn + s1 * cs;
    } else if (f < 2 * E) {
        int fk = f - E;
        int j = (fk & 63) >> 1;
        float freq = __expf(-(float)j * (logf(10000.0f) / 32.0f));
        float sn, cs;
        sincosf((float)(pos + t) * freq, &sn, &cs);
        int slot = (pos + t) % L;
        size_t off = ((size_t)b * L + slot) * E + fk;
        kcache[off]     = s0 * cs - s1 * sn;
        kcache[off + 1] = s0 * sn + s1 * cs;
    } else {
        int fv = f - 2 * E;
        int slot = (pos + t) % L;
        size_t off = ((size_t)b * L + slot) * E + fv;
        vcache[off]     = s0;
        vcache[off + 1] = s1;
    }
}

// -------- LayerNorm (layer-0 entry) --------
__global__ void ln_kernel(const float* __restrict__ X,
                          const float* __restrict__ w,
                          const float* __restrict__ b,
                          float* __restrict__ Y)
{
    int tok = blockIdx.x;
    int tid = threadIdx.x;
    float wv[4], bv[4];
    #pragma unroll
    for (int j = 0; j < 4; j++) { wv[j] = w[tid + 256 * j]; bv[j] = b[tid + 256 * j]; }
    GDW();
    const float* x = X + (size_t)tok * E;
    float v[4];
    #pragma unroll
    for (int j = 0; j < 4; j++) v[j] = x[tid + 256 * j];
    float s = v[0] + v[1] + v[2] + v[3];
    #pragma unroll
    for (int o = 16; o > 0; o >>= 1) s += __shfl_xor_sync(0xffffffffu, s, o);
    __shared__ float ws[8];
    if ((tid & 31) == 0) ws[tid >> 5] = s;
    __syncthreads();
    float mean = (ws[0]+ws[1]+ws[2]+ws[3]+ws[4]+ws[5]+ws[6]+ws[7]) * (1.0f / E);
    float s2 = 0.f;
    #pragma unroll
    for (int j = 0; j < 4; j++) { float d = v[j] - mean; s2 += d * d; }
    #pragma unroll
    for (int o = 16; o > 0; o >>= 1) s2 += __shfl_xor_sync(0xffffffffu, s2, o);
    __syncthreads();
    if ((tid & 31) == 0) ws[tid >> 5] = s2;
    __syncthreads();
    float var = (ws[0]+ws[1]+ws[2]+ws[3]+ws[4]+ws[5]+ws[6]+ws[7]) * (1.0f / E);
    float r = rsqrtf(var + 1e-5f);
    #pragma unroll
    for (int j = 0; j < 4; j++) {
        int idx = tid + 256 * j;
        Y[(size_t)tok * E + idx] = (v[j] - mean) * r * wv[j] + bv[j];
    }
}

// -------- fused: x += sum(8 partials); xn = LN(x) --------
__global__ void reduce_ln_kernel(const float* __restrict__ part,
                                 float* __restrict__ x,
                                 const float* __restrict__ w,
                                 const float* __restrict__ b,
                                 float* __restrict__ xn)
{
    int tok = blockIdx.x;
    int tid = threadIdx.x;
    float wv[4], bv[4];
    #pragma unroll
    for (int j = 0; j < 4; j++) { wv[j] = w[tid + 256 * j]; bv[j] = b[tid + 256 * j]; }
    GDW();
    float v[4];
    #pragma unroll
    for (int j = 0; j < 4; j++) {
        int idx = tid + 256 * j;
        float p = 0.f;
        #pragma unroll
        for (int k = 0; k < 8; k++) p += part[((size_t)(k * 32 + tok)) * E + idx];
        float xv = x[(size_t)tok * E + idx] + p;
        x[(size_t)tok * E + idx] = xv;
        v[j] = xv;
    }
    float s = v[0] + v[1] + v[2] + v[3];
    #pragma unroll
    for (int o = 16; o > 0; o >>= 1) s += __shfl_xor_sync(0xffffffffu, s, o);
    __shared__ float ws[8];
    if ((tid & 31) == 0) ws[tid >> 5] = s;
    __syncthreads();
    float mean = (ws[0]+ws[1]+ws[2]+ws[3]+ws[4]+ws[5]+ws[6]+ws[7]) * (1.0f / E);
    float s2 = 0.f;
    #pragma unroll
    for (int j = 0; j < 4; j++) { float d = v[j] - mean; s2 += d * d; }
    #pragma unroll
    for (int o = 16; o > 0; o >>= 1) s2 += __shfl_xor_sync(0xffffffffu, s2, o);
    __syncthreads();
    if ((tid & 31) == 0) ws[tid >> 5] = s2;
    __syncthreads();
    float var = (ws[0]+ws[1]+ws[2]+ws[3]+ws[4]+ws[5]+ws[6]+ws[7]) * (1.0f / E);
    float r = rsqrtf(var + 1e-5f);
    #pragma unroll
    for (int j = 0; j < 4; j++) {
        int idx = tid + 256 * j;
        xn[(size_t)tok * E + idx] = (v[j] - mean) * r * wv[j] + bv[j];
    }
}

// -------- fused: x += partials; out_x = LN(x); eos dot --------
__global__ void reduce_ln_eos_kernel(const float* __restrict__ part,
                                     float* __restrict__ x,
                                     const float* __restrict__ w,
                                     const float* __restrict__ b,
                                     const float* __restrict__ ew,
                                     const float* __restrict__ eb,
                                     float* __restrict__ Y,
                                     float* __restrict__ out_eos)
{
    int tok = blockIdx.x;
    int tid = threadIdx.x;
    float wv[4], bv[4], ev[4];
    #pragma unroll
    for (int j = 0; j < 4; j++) {
        wv[j] = w[tid + 256 * j];
        bv[j] = b[tid + 256 * j];
        ev[j] = ew[tid + 256 * j];
    }
    GDW();
    float v[4];
    #pragma unroll
    for (int j = 0; j < 4; j++) {
        int idx = tid + 256 * j;
        float p = 0.f;
        #pragma unroll
        for (int k = 0; k < 8; k++) p += part[((size_t)(k * 32 + tok)) * E + idx];
        v[j] = x[(size_t)tok * E + idx] + p;
    }
    float s = v[0] + v[1] + v[2] + v[3];
    #pragma unroll
    for (int o = 16; o > 0; o >>= 1) s += __shfl_xor_sync(0xffffffffu, s, o);
    __shared__ float ws[8];
    if ((tid & 31) == 0) ws[tid >> 5] = s;
    __syncthreads();
    float mean = (ws[0]+ws[1]+ws[2]+ws[3]+ws[4]+ws[5]+ws[6]+ws[7]) * (1.0f / E);
    float s2 = 0.f;
    #pragma unroll
    for (int j = 0; j < 4; j++) { float d = v[j] - mean; s2 += d * d; }
    #pragma unroll
    for (int o = 16; o > 0; o >>= 1) s2 += __shfl_xor_sync(0xffffffffu, s2, o);
    __syncthreads();
    if ((tid & 31) == 0) ws[tid >> 5] = s2;
    __syncthreads();
    float var = (ws[0]+ws[1]+ws[2]+ws[3]+ws[4]+ws[5]+ws[6]+ws[7]) * (1.0f / E);
    float r = rsqrtf(var + 1e-5f);
    float ed = 0.f;
    #pragma unroll
    for (int j = 0; j < 4; j++) {
        int idx = tid + 256 * j;
        float y = (v[j] - mean) * r * wv[j] + bv[j];
        Y[(size_t)tok * E + idx] = y;
        ed += y * ev[j];
    }
    #pragma unroll
    for (int o = 16; o > 0; o >>= 1) ed += __shfl_xor_sync(0xffffffffu, ed, o);
    __syncthreads();
    if ((tid & 31) == 0) ws[tid >> 5] = ed;
    __syncthreads();
    if (tid == 0)
        out_eos[tok] = ws[0]+ws[1]+ws[2]+ws[3]+ws[4]+ws[5]+ws[6]+ws[7] + eb[0];
}

// -------- Attention partial: grid 512, K/V from output cache --------
#define CMAX 260
__global__ void attn_part_kernel(const float* __restrict__ q,
                                 const float* __restrict__ kc,
                                 const float* __restrict__ vc,
                                 const int* __restrict__ pos_l,
                                 float* __restrict__ po,
                                 float* __restrict__ gm,
                                 float* __restrict__ gl)
{
    __shared__ float qs[4][64];
    __shared__ float sc[4][CMAX];
    __shared__ float red[8];
    __shared__ float mt[4], lt[4];
    __shared__ float vpart[4][4][64];

    int bh   = blockIdx.x & 127;
    int cidx = blockIdx.x >> 7;
    int b = bh >> 4, h = bh & 15;
    int tid = threadIdx.x;
    int pos = pos_l[b];
    GDW();
    int slen = pos + T;
    int chunk = (slen + 3) >> 2;
    int s0 = cidx * chunk;
    int s1 = min(slen, s0 + chunk);
    int len = s1 - s0;
    int gbase = (bh * 4 + cidx) * 4;

    if (len <= 0) {
        po[(size_t)gbase * 64 + tid] = 0.f;
        if (tid < 4) { gm[gbase + tid] = -1e30f; gl[gbase + tid] = 0.f; }
        return;
    }

    {
        int t = tid >> 6, d = tid & 63;
        qs[t][d] = q[((size_t)(b * T + t) * E) + h * D + d];
    }
    __syncthreads();

    const float scale = 0.125f;
    for (int i = tid; i < len; i += 256) {
        int s = s0 + i;
        const float4* kr = (const float4*)(kc + ((size_t)b * L + s) * E + h * D);
        float d0 = 0.f, d1 = 0.f, d2 = 0.f, d3 = 0.f;
        #pragma unroll
        for (int i4 = 0; i4 < 16; i4++) {
            float4 kv = kr[i4];
            int d = i4 * 4;
            d0 += qs[0][d]*kv.x + qs[0][d+1]*kv.y + qs[0][d+2]*kv.z + qs[0][d+3]*kv.w;
            d1 += qs[1][d]*kv.x + qs[1][d+1]*kv.y + qs[1][d+2]*kv.z + qs[1][d+3]*kv.w;
            d2 += qs[2][d]*kv.x + qs[2][d+1]*kv.y + qs[2][d+2]*kv.z + qs[2][d+3]*kv.w;
            d3 += qs[3][d]*kv.x + qs[3][d+1]*kv.y + qs[3][d+2]*kv.z + qs[3][d+3]*kv.w;
        }
        sc[0][i] = (s <= pos + 0) ? d0 * scale : -1e30f;
        sc[1][i] = (s <= pos + 1) ? d1 * scale : -1e30f;
        sc[2][i] = (s <= pos + 2) ? d2 * scale : -1e30f;
        sc[3][i] = (s <= pos + 3) ? d3 * scale : -1e30f;
    }
    __syncthreads();

    #pragma unroll
    for (int t = 0; t < 4; t++) {
        float m = -1e30f;
        for (int i = tid; i < len; i += 256) m = fmaxf(m, sc[t][i]);
        #pragma unroll
        for (int o = 16; o > 0; o >>= 1) m = fmaxf(m, __shfl_xor_sync(0xffffffffu, m, o));
        if ((tid & 31) == 0) red[tid >> 5] = m;
        __syncthreads();
        m = fmaxf(fmaxf(fmaxf(red[0], red[1]), fmaxf(red[2], red[3])),
                  fmaxf(fmaxf(red[4], red[5]), fmaxf(red[6], red[7])));
        float ssum = 0.f;
        for (int i = tid; i < len; i += 256) {
            float e = __expf(sc[t][i] - m);
            sc[t][i] = e;
            ssum += e;
        }
        #pragma unroll
        for (int o = 16; o > 0; o >>= 1) ssum += __shfl_xor_sync(0xffffffffu, ssum, o);
        __syncthreads();
        if ((tid & 31) == 0) red[tid >> 5] = ssum;
        __syncthreads();
        if (tid == 0) {
            mt[t] = m;
            lt[t] = red[0]+red[1]+red[2]+red[3]+red[4]+red[5]+red[6]+red[7];
        }
        __syncthreads();
    }

    {
        int sg = tid >> 6, d = tid & 63;
        int q4 = (len + 3) >> 2;
        int i0 = sg * q4;
        int i1 = min(len, i0 + q4);
        const float* vp = vc + ((size_t)b * L + s0) * E + h * D + d;
        float a0 = 0.f, a1 = 0.f, a2 = 0.f, a3 = 0.f;
        int i = i0;
        for (; i + 2 <= i1; i += 2) {
            float v0 = vp[(size_t)i * E];
            float v1 = vp[(size_t)(i + 1) * E];
            a0 += sc[0][i] * v0 + sc[0][i+1] * v1;
            a1 += sc[1][i] * v0 + sc[1][i+1] * v1;
            a2 += sc[2][i] * v0 + sc[2][i+1] * v1;
            a3 += sc[3][i] * v0 + sc[3][i+1] * v1;
        }
        if (i < i1) {
            float v0 = vp[(size_t)i * E];
            a0 += sc[0][i] * v0;
            a1 += sc[1][i] * v0;
            a2 += sc[2][i] * v0;
            a3 += sc[3][i] * v0;
        }
        vpart[sg][0][d] = a0;
        vpart[sg][1][d] = a1;
        vpart[sg][2][d] = a2;
        vpart[sg][3][d] = a3;
    }
    __syncthreads();
    {
        int t = tid >> 6, d = tid & 63;
        float sum = vpart[0][t][d] + vpart[1][t][d] + vpart[2][t][d] + vpart[3][t][d];
        po[((size_t)(gbase + t)) * 64 + d] = sum;
        if (tid < 4) { gm[gbase + tid] = mt[tid]; gl[gbase + tid] = lt[tid]; }
    }
}

// -------- host: PDL launch helper --------
template<typename F, typename... Args>
static inline void pdl(dim3 g, dim3 blk, F f, Args... args)
{
    cudaLaunchAttribute at[1];
    at[0].id = cudaLaunchAttributeProgrammaticStreamSerialization;
    at[0].val.programmaticStreamSerializationAllowed = 1;
    cudaLaunchConfig_t cfg = {};
    cfg.gridDim = g;
    cfg.blockDim = blk;
    cfg.dynamicSmemBytes = 0;
    cfg.stream = 0;
    cfg.attrs = at;
    cfg.numAttrs = 1;
    cudaLaunchKernelEx(&cfg, f, args...);
}

extern "C" void kernel_launch(void* const* d_in, const int* in_sizes, int n_in,
                              void* d_out, int out_size)
{
    const float* seq       = (const float*)d_in[0];
    const float* bos       = (const float*)d_in[1];
    const float* caches    = (const float*)d_in[2];
    const int*   positions = (const int*)  d_in[3];
    const float* in_w      = (const float*)d_in[4];
    const float* ip_w      = (const float*)d_in[5];
    const float* op_w      = (const float*)d_in[6];
    const float* n1w       = (const float*)d_in[7];
    const float* n1b       = (const float*)d_in[8];
    const float* n2w       = (const float*)d_in[9];
    const float* n2b       = (const float*)d_in[10];
    const float* l1_w      = (const float*)d_in[11];
    const float* l2_w      = (const float*)d_in[12];
    const float* on_w      = (const float*)d_in[13];
    const float* on_b      = (const float*)d_in[14];
    const float* eos_w     = (const float*)d_in[15];
    const float* eos_b     = (const float*)d_in[16];

    float* out = (float*)d_out;
    const size_t cache_elems = (size_t)NL * 2 * B * L * E;
    float* out_x     = out;
    float* out_eos   = out + (size_t)NTOK * E;
    float* out_cache = out_eos + NTOK;
    float* out_pos   = out_cache + cache_elems;

    float *px, *pxn, *pq, *pseq, *ppart, *ppart2, *ppo, *pm, *pl;
    cudaGetSymbolAddress((void**)&px,     g_x);
    cudaGetSymbolAddress((void**)&pxn,    g_xn);
    cudaGetSymbolAddress((void**)&pq,     g_q);
    cudaGetSymbolAddress((void**)&pseq,   g_seq);
    cudaGetSymbolAddress((void**)&ppart,  g_part);
    cudaGetSymbolAddress((void**)&ppart2, g_part2);
    cudaGetSymbolAddress((void**)&ppo,    g_po);
    cudaGetSymbolAddress((void**)&pm,     g_m);
    cudaGetSymbolAddress((void**)&pl,     g_l);

    long nf4 = (long)(cache_elems / 4);
    cache_copy_kernel<<<(unsigned)((nf4 + 255) / 256), 256>>>((const float4*)caches,
                                                              (float4*)out_cache, nf4);

    pdl(dim3(5), dim3(256), prep_pos_kernel, seq, bos, positions, pseq, out_pos);
    pdl(dim3(E / 64, 1), dim3(256), gemv_kernel<1, 0>,
        (const float*)pseq, in_w, px, (float*)nullptr, (int)INDIM, (int)E,
        (const float*)nullptr, (const float*)nullptr);
    pdl(dim3(NTOK), dim3(256), ln_kernel, (const float*)px, n1w, n1b, pxn);

    for (int i = 0; i < NL; i++) {
        const float* ipw = ip_w + (size_t)i * 3 * E * E;
        const float* opw = op_w + (size_t)i * E * E;
        const float* l1  = l1_w + (size_t)i * FF * E;
        const float* l2  = l2_w + (size_t)i * E * FF;
        float* kcache = out_cache + ((size_t)i * 2 + 0) * B * L * E;
        float* vcache = out_cache + ((size_t)i * 2 + 1) * B * L * E;
        const int* posl = positions + i * B;

        // qkv: K=1024, N=3072, split-K=4 -> 192 blocks
        pdl(dim3(3 * E / 64, 4), dim3(256), gemv_kernel<4, 0>,
            (const float*)pxn, ipw, (float*)nullptr, ppart, (int)E, (int)(3 * E),
            (const float*)nullptr, (const float*)nullptr);
        pdl(dim3(192), dim3(256), reduce_rope_kernel,
            (const float*)ppart, posl, pq, kcache, vcache);

        pdl(dim3(512), dim3(256), attn_part_kernel,
            (const float*)pq, (const float*)kcache, (const float*)vcache, posl,
            ppo, pm, pl);

        // op: K=1024, N=1024, split-K=8; X = softmax-combine of po (XMODE=2)
        pdl(dim3(E / 64, 8), dim3(256), gemv_kernel<8, 2>,
            (const float*)ppo, opw, (float*)nullptr, ppart2, (int)E, (int)E,
            (const float*)pm, (const float*)pl);
        pdl(dim3(NTOK), dim3(256), reduce_ln_kernel,
            (const float*)ppart2, px, n2w + (size_t)i * E, n2b + (size_t)i * E, pxn);

        // l1: K=1024, N=4096, split-K=2 -> raw partials
        pdl(dim3(FF / 64, 2), dim3(256), gemv_kernel<2, 0>,
            (const float*)pxn, l1, (float*)nullptr, ppart, (int)E, (int)FF,
            (const float*)nullptr, (const float*)nullptr);

        // l2: K=4096, N=1024, split-K=8; X = gelu(part0+part1) (XMODE=1)
        pdl(dim3(E / 64, 8), dim3(256), gemv_kernel<8, 1>,
            (const float*)ppart, l2, (float*)nullptr, ppart2, (int)FF, (int)E,
            (const float*)nullptr, (const float*)nullptr);

        if (i + 1 < NL) {
            pdl(dim3(NTOK), dim3(256), reduce_ln_kernel,
                (const float*)ppart2, px,
                n1w + (size_t)(i + 1) * E, n1b + (size_t)(i + 1) * E, pxn);
        } else {
            pdl(dim3(NTOK), dim3(256), reduce_ln_eos_kernel,
                (const float*)ppart2, px, on_w, on_b, eos_w, eos_b,
                out_x, out_eos);
        }
    }
}

// round 14
// speedup vs baseline: 1.0552x; 1.0552x over previous
#include <cuda_runtime.h>
#include <math.h>

#define NL 6
#define B  8
#define T  4
#define L  2048
#define H  16
#define D  64
#define E  1024
#define FF 4096
#define INDIM 32
#define NTOK 32
#define DEPTH 3

#define CACHE_F4 50331648LL            // NL*2*B*L*E/4

#define GDW() asm volatile("griddepcontrol.wait;" ::: "memory")

// -------- scratch (device globals) --------
__device__ __align__(16) float g_x   [NTOK * E];
__device__ __align__(16) float g_xn  [NTOK * E];
__device__ __align__(16) float g_q   [NTOK * E];
__device__ __align__(16) float g_attn[NTOK * E];
__device__ __align__(16) float g_h   [NTOK * FF];
__device__ __align__(16) float g_seq [NTOK * INDIM];
__device__ __align__(16) float g_part[524288];
__device__ __align__(16) float g_po  [B * H * 4 * T * D];
__device__ float g_m [B * H * 4 * T];
__device__ float g_l [B * H * 4 * T];

// -------- helpers --------
__device__ __forceinline__ unsigned long long pk2(float lo, float hi) {
    unsigned long long r;
    asm("mov.b64 %0, {%1, %2};" : "=l"(r) : "f"(lo), "f"(hi));
    return r;
}
__device__ __forceinline__ void fma2(unsigned long long& d,
                                     unsigned long long a,
                                     unsigned long long b) {
    asm("fma.rn.f32x2 %0, %1, %2, %3;" : "=l"(d) : "l"(a), "l"(b), "l"(d));
}
__device__ __forceinline__ float2 upk(unsigned long long v) {
    float2 f;
    asm("mov.b64 {%0, %1}, %2;" : "=f"(f.x), "=f"(f.y) : "l"(v));
    return f;
}
__device__ __forceinline__ void cpa16(unsigned dst, const void* src) {
    asm volatile("cp.async.ca.shared.global [%0], [%1], 16;" :: "r"(dst), "l"(src));
}
#define CP_COMMIT() asm volatile("cp.async.commit_group;")
#define CP_WAIT1()  asm volatile("cp.async.wait_group 1;")

// -------- bulk cache copy with NaN cleaning --------
__global__ void cache_copy_kernel(const float4* __restrict__ in,
                                  float4* __restrict__ out, long n)
{
    long i = (long)blockIdx.x * blockDim.x + threadIdx.x;
    if (i < n) {
        float4 v = in[i];
        v.x = isnan(v.x) ? 0.0f : v.x;
        v.y = isnan(v.y) ? 0.0f : v.y;
        v.z = isnan(v.z) ? 0.0f : v.z;
        v.w = isnan(v.w) ? 0.0f : v.w;
        out[i] = v;
    }
}

// -------- prep seq + new positions --------
__global__ void prep_pos_kernel(const float* __restrict__ seq,
                                const float* __restrict__ bos,
                                const int* __restrict__ positions,
                                float* __restrict__ out_seq,
                                float* __restrict__ out_pos)
{
    if (blockIdx.x < 4) {
        int i = blockIdx.x * 256 + threadIdx.x;
        float v = seq[i];
        out_seq[i] = isnan(v) ? bos[i & (INDIM - 1)] : v;
    } else {
        int i = threadIdx.x;
        if (i < NL * B) out_pos[i] = (float)(positions[i] + T);
    }
}

// ======== GEMM: Y[32,N] = X[32,K] @ W[N,K]^T ========
// W: cp.async 3-stage pipeline, prefetched BEFORE the PDL wait (W-only groups).
// X: regular float4 loads post-wait, 1-ahead register prefetch, stored
// transposed-packed XsP[k2][row] (low-conflict). f32x2 compute.
template<int KSPLIT>
__global__ void gemv_kernel(const float* __restrict__ X,
                            const float* __restrict__ W,
                            float* __restrict__ Y,
                            float* __restrict__ part,
                            int K, int N)
{
    __shared__ __align__(16) unsigned long long XsP[DEPTH][16][33];
    __shared__ __align__(16) float Ws[DEPTH][64][36];

    const int t    = threadIdx.x;
    const int lane = t & 31;
    const int c0   = (t >> 5) * 8;
    const int n0   = blockIdx.x * 64;
    const int Kc   = K / KSPLIT;
    const int kbase = blockIdx.y * Kc;
    const int nch  = Kc >> 5;

    const int xrow = t >> 3, xk4 = (t & 7) * 4;
    const int wrow = t >> 2, wk  = (t & 3) * 8;

    const float* xsrc = X + (size_t)xrow * K + kbase + xk4;
    const float* wsrc = W + (size_t)(n0 + wrow) * K + kbase + wk;

    const unsigned wbase = (unsigned)__cvta_generic_to_shared(&Ws[0][0][0])
                         + (unsigned)((wrow * 36 + wk) * 4);
    const unsigned WST = 64 * 36 * 4;

    // ---- W prefetch stages 0..DEPTH-2 (launch-independent, pre-wait) ----
    #pragma unroll
    for (int p = 0; p < DEPTH - 1; p++) {
        if (p < nch) {
            cpa16(wbase + p * WST, wsrc + (size_t)p * 32);
            cpa16(wbase + p * WST + 16, wsrc + (size_t)p * 32 + 4);
        }
        CP_COMMIT();   // W-only groups
    }
    GDW();   // predecessor output (X) now valid

    float4 xr = make_float4(0.f, 0.f, 0.f, 0.f);
    if (0 < nch) xr = *(const float4*)xsrc;

    unsigned long long acc[8];
    #pragma unroll
    for (int c = 0; c < 8; c++) acc[c] = 0ULL;

    int st = 0;
    int si = DEPTH - 1;
    for (int ch = 0; ch < nch; ch++) {
        CP_WAIT1();                       // W stage for chunk ch resident
        XsP[st][(xk4 >> 1)    ][xrow] = pk2(xr.x, xr.y);
        XsP[st][(xk4 >> 1) + 1][xrow] = pk2(xr.z, xr.w);
        __syncthreads();

        if (ch + 1 < nch) xr = *(const float4*)(xsrc + (size_t)(ch + 1) * 32);

        #pragma unroll
        for (int p = 0; p < 16; p += 2) {
            unsigned long long x0 = XsP[st][p][lane];
            unsigned long long x1 = XsP[st][p + 1][lane];
            #pragma unroll
            for (int c = 0; c < 8; c++) {
                longlong2 w = *(const longlong2*)&Ws[st][c0 + c][2 * p];
                fma2(acc[c], x0, (unsigned long long)w.x);
                fma2(acc[c], x1, (unsigned long long)w.y);
            }
        }
        __syncthreads();

        int nc = ch + DEPTH - 1;
        if (nc < nch) {
            cpa16(wbase + si * WST, wsrc + (size_t)nc * 32);
            cpa16(wbase + si * WST + 16, wsrc + (size_t)nc * 32 + 4);
        }
        CP_COMMIT();
        st = (st == DEPTH - 1) ? 0 : st + 1;
        si = (si == DEPTH - 1) ? 0 : si + 1;
    }

    if (KSPLIT == 1) {
        #pragma unroll
        for (int c = 0; c < 8; c++) {
            float2 p = upk(acc[c]);
            Y[(size_t)lane * N + n0 + c0 + c] = p.x + p.y;
        }
    } else {
        float* pp = part + ((size_t)blockIdx.y * 32 + lane) * N + n0 + c0;
        #pragma unroll
        for (int c = 0; c < 8; c++) {
            float2 p = upk(acc[c]);
            pp[c] = p.x + p.y;
        }
    }
}

// sum split-K partials + gelu (l1 path)
template<int KS>
__global__ void reduce_gelu_kernel(const float* __restrict__ part,
                                   float* __restrict__ Y, int N)
{
    GDW();
    int i = blockIdx.x * 256 + threadIdx.x;
    if (i >= 32 * N) return;
    int r = i / N, n = i - r * N;
    float s = 0.f;
    #pragma unroll
    for (int k = 0; k < KS; k++) s += part[((size_t)k * 32 + r) * N + n];
    Y[i] = 0.5f * s * (1.0f + erff(s * 0.70710678118654752f));
}

// -------- fused qkv split-K(4) reduce + RoPE + cache scatter --------
__global__ void reduce_rope_kernel(const float* __restrict__ part,
                                   const int* __restrict__ pos_l,
                                   float* __restrict__ qout,
                                   float* __restrict__ kcache,
                                   float* __restrict__ vcache)
{
    int id = blockIdx.x * 256 + threadIdx.x;
    int tok = id / 1536;
    int f   = (id - tok * 1536) * 2;
    int b = tok >> 2, t = tok & 3;
    int pos = pos_l[b];
    GDW();
    float s0 = 0.f, s1 = 0.f;
    #pragma unroll
    for (int k = 0; k < 4; k++) {
        const float* p = part + ((size_t)(k * 32 + tok) * 3072) + f;
        s0 += p[0];
        s1 += p[1];
    }
    if (f < E) {
        int j = (f & 63) >> 1;
        float freq = __expf(-(float)j * (logf(10000.0f) / 32.0f));
        float sn, cs;
        sincosf((float)(pos + t) * freq, &sn, &cs);
        qout[(size_t)tok * E + f]     = s0 * cs - s1 * sn;
        qout[(size_t)tok * E + f + 1] = s0 * sn + s1 * cs;
    } else if (f < 2 * E) {
        int fk = f - E;
        int j = (fk & 63) >> 1;
        float freq = __expf(-(float)j * (logf(10000.0f) / 32.0f));
        float sn, cs;
        sincosf((float)(pos + t) * freq, &sn, &cs);
        int slot = (pos + t) % L;
        size_t off = ((size_t)b * L + slot) * E + fk;
        kcache[off]     = s0 * cs - s1 * sn;
        kcache[off + 1] = s0 * sn + s1 * cs;
    } else {
        int fv = f - 2 * E;
        int slot = (pos + t) % L;
        size_t off = ((size_t)b * L + slot) * E + fv;
        vcache[off]     = s0;
        vcache[off + 1] = s1;
    }
}

// -------- LayerNorm (layer-0 entry) --------
__global__ void ln_kernel(const float* __restrict__ X,
                          const float* __restrict__ w,
                          const float* __restrict__ b,
                          float* __restrict__ Y)
{
    int tok = blockIdx.x;
    int tid = threadIdx.x;
    float wv[4], bv[4];
    #pragma unroll
    for (int j = 0; j < 4; j++) { wv[j] = w[tid + 256 * j]; bv[j] = b[tid + 256 * j]; }
    GDW();
    const float* x = X + (size_t)tok * E;
    float v[4];
    #pragma unroll
    for (int j = 0; j < 4; j++) v[j] = x[tid + 256 * j];
    float s = v[0] + v[1] + v[2] + v[3];
    #pragma unroll
    for (int o = 16; o > 0; o >>= 1) s += __shfl_xor_sync(0xffffffffu, s, o);
    __shared__ float ws[8];
    if ((tid & 31) == 0) ws[tid >> 5] = s;
    __syncthreads();
    float mean = (ws[0]+ws[1]+ws[2]+ws[3]+ws[4]+ws[5]+ws[6]+ws[7]) * (1.0f / E);
    float s2 = 0.f;
    #pragma unroll
    for (int j = 0; j < 4; j++) { float d = v[j] - mean; s2 += d * d; }
    #pragma unroll
    for (int o = 16; o > 0; o >>= 1) s2 += __shfl_xor_sync(0xffffffffu, s2, o);
    __syncthreads();
    if ((tid & 31) == 0) ws[tid >> 5] = s2;
    __syncthreads();
    float var = (ws[0]+ws[1]+ws[2]+ws[3]+ws[4]+ws[5]+ws[6]+ws[7]) * (1.0f / E);
    float r = rsqrtf(var + 1e-5f);
    #pragma unroll
    for (int j = 0; j < 4; j++) {
        int idx = tid + 256 * j;
        Y[(size_t)tok * E + idx] = (v[j] - mean) * r * wv[j] + bv[j];
    }
}

// -------- fused: x += sum(8 partials); xn = LN(x) --------
__global__ void reduce_ln_kernel(const float* __restrict__ part,
                                 float* __restrict__ x,
                                 const float* __restrict__ w,
                                 const float* __restrict__ b,
                                 float* __restrict__ xn)
{
    int tok = blockIdx.x;
    int tid = threadIdx.x;
    float wv[4], bv[4];
    #pragma unroll
    for (int j = 0; j < 4; j++) { wv[j] = w[tid + 256 * j]; bv[j] = b[tid + 256 * j]; }
    GDW();
    float v[4];
    #pragma unroll
    for (int j = 0; j < 4; j++) {
        int idx = tid + 256 * j;
        float p = 0.f;
        #pragma unroll
        for (int k = 0; k < 8; k++) p += part[((size_t)(k * 32 + tok)) * E + idx];
        float xv = x[(size_t)tok * E + idx] + p;
        x[(size_t)tok * E + idx] = xv;
        v[j] = xv;
    }
    float s = v[0] + v[1] + v[2] + v[3];
    #pragma unroll
    for (int o = 16; o > 0; o >>= 1) s += __shfl_xor_sync(0xffffffffu, s, o);
    __shared__ float ws[8];
    if ((tid & 31) == 0) ws[tid >> 5] = s;
    __syncthreads();
    float mean = (ws[0]+ws[1]+ws[2]+ws[3]+ws[4]+ws[5]+ws[6]+ws[7]) * (1.0f / E);
    float s2 = 0.f;
    #pragma unroll
    for (int j = 0; j < 4; j++) { float d = v[j] - mean; s2 += d * d; }
    #pragma unroll
    for (int o = 16; o > 0; o >>= 1) s2 += __shfl_xor_sync(0xffffffffu, s2, o);
    __syncthreads();
    if ((tid & 31) == 0) ws[tid >> 5] = s2;
    __syncthreads();
    float var = (ws[0]+ws[1]+ws[2]+ws[3]+ws[4]+ws[5]+ws[6]+ws[7]) * (1.0f / E);
    float r = rsqrtf(var + 1e-5f);
    #pragma unroll
    for (int j = 0; j < 4; j++) {
        int idx = tid + 256 * j;
        xn[(size_t)tok * E + idx] = (v[j] - mean) * r * wv[j] + bv[j];
    }
}

// -------- fused: x += partials; out_x = LN(x); eos dot --------
__global__ void reduce_ln_eos_kernel(const float* __restrict__ part,
                                     float* __restrict__ x,
                                     const float* __restrict__ w,
                                     const float* __restrict__ b,
                                     const float* __restrict__ ew,
                                     const float* __restrict__ eb,
                                     float* __restrict__ Y,
                                     float* __restrict__ out_eos)
{
    int tok = blockIdx.x;
    int tid = threadIdx.x;
    float wv[4], bv[4], ev[4];
    #pragma unroll
    for (int j = 0; j < 4; j++) {
        wv[j] = w[tid + 256 * j];
        bv[j] = b[tid + 256 * j];
        ev[j] = ew[tid + 256 * j];
    }
    GDW();
    float v[4];
    #pragma unroll
    for (int j = 0; j < 4; j++) {
        int idx = tid + 256 * j;
        float p = 0.f;
        #pragma unroll
        for (int k = 0; k < 8; k++) p += part[((size_t)(k * 32 + tok)) * E + idx];
        v[j] = x[(size_t)tok * E + idx] + p;
    }
    float s = v[0] + v[1] + v[2] + v[3];
    #pragma unroll
    for (int o = 16; o > 0; o >>= 1) s += __shfl_xor_sync(0xffffffffu, s, o);
    __shared__ float ws[8];
    if ((tid & 31) == 0) ws[tid >> 5] = s;
    __syncthreads();
    float mean = (ws[0]+ws[1]+ws[2]+ws[3]+ws[4]+ws[5]+ws[6]+ws[7]) * (1.0f / E);
    float s2 = 0.f;
    #pragma unroll
    for (int j = 0; j < 4; j++) { float d = v[j] - mean; s2 += d * d; }
    #pragma unroll
    for (int o = 16; o > 0; o >>= 1) s2 += __shfl_xor_sync(0xffffffffu, s2, o);
    __syncthreads();
    if ((tid & 31) == 0) ws[tid >> 5] = s2;
    __syncthreads();
    float var = (ws[0]+ws[1]+ws[2]+ws[3]+ws[4]+ws[5]+ws[6]+ws[7]) * (1.0f / E);
    float r = rsqrtf(var + 1e-5f);
    float ed = 0.f;
    #pragma unroll
    for (int j = 0; j < 4; j++) {
        int idx = tid + 256 * j;
        float y = (v[j] - mean) * r * wv[j] + bv[j];
        Y[(size_t)tok * E + idx] = y;
        ed += y * ev[j];
    }
    #pragma unroll
    for (int o = 16; o > 0; o >>= 1) ed += __shfl_xor_sync(0xffffffffu, ed, o);
    __syncthreads();
    if ((tid & 31) == 0) ws[tid >> 5] = ed;
    __syncthreads();
    if (tid == 0)
        out_eos[tok] = ws[0]+ws[1]+ws[2]+ws[3]+ws[4]+ws[5]+ws[6]+ws[7] + eb[0];
}

// -------- Attention partial: grid 512, K/V from output cache --------
#define CMAX 260
__global__ void attn_part_kernel(const float* __restrict__ q,
                                 const float* __restrict__ kc,
                                 const float* __restrict__ vc,
                                 const int* __restrict__ pos_l,
                                 float* __restrict__ po,
                                 float* __restrict__ gm,
                                 float* __restrict__ gl)
{
    __shared__ float qs[4][64];
    __shared__ float sc[4][CMAX];
    __shared__ float red[8];
    __shared__ float mt[4], lt[4];
    __shared__ float vpart[4][4][64];

    int bh   = blockIdx.x & 127;
    int cidx = blockIdx.x >> 7;
    int b = bh >> 4, h = bh & 15;
    int tid = threadIdx.x;
    int pos = pos_l[b];
    GDW();
    int slen = pos + T;
    int chunk = (slen + 3) >> 2;
    int s0 = cidx * chunk;
    int s1 = min(slen, s0 + chunk);
    int len = s1 - s0;
    int gbase = (bh * 4 + cidx) * 4;

    if (len <= 0) {
        po[(size_t)gbase * 64 + tid] = 0.f;
        if (tid < 4) { gm[gbase + tid] = -1e30f; gl[gbase + tid] = 0.f; }
        return;
    }

    {
        int t = tid >> 6, d = tid & 63;
        qs[t][d] = q[((size_t)(b * T + t) * E) + h * D + d];
    }
    __syncthreads();

    const float scale = 0.125f;
    for (int i = tid; i < len; i += 256) {
        int s = s0 + i;
        const float4* kr = (const float4*)(kc + ((size_t)b * L + s) * E + h * D);
        float d0 = 0.f, d1 = 0.f, d2 = 0.f, d3 = 0.f;
        #pragma unroll
        for (int i4 = 0; i4 < 16; i4++) {
            float4 kv = kr[i4];
            int d = i4 * 4;
            d0 += qs[0][d]*kv.x + qs[0][d+1]*kv.y + qs[0][d+2]*kv.z + qs[0][d+3]*kv.w;
            d1 += qs[1][d]*kv.x + qs[1][d+1]*kv.y + qs[1][d+2]*kv.z + qs[1][d+3]*kv.w;
            d2 += qs[2][d]*kv.x + qs[2][d+1]*kv.y + qs[2][d+2]*kv.z + qs[2][d+3]*kv.w;
            d3 += qs[3][d]*kv.x + qs[3][d+1]*kv.y + qs[3][d+2]*kv.z + qs[3][d+3]*kv.w;
        }
        sc[0][i] = (s <= pos + 0) ? d0 * scale : -1e30f;
        sc[1][i] = (s <= pos + 1) ? d1 * scale : -1e30f;
        sc[2][i] = (s <= pos + 2) ? d2 * scale : -1e30f;
        sc[3][i] = (s <= pos + 3) ? d3 * scale : -1e30f;
    }
    __syncthreads();

    #pragma unroll
    for (int t = 0; t < 4; t++) {
        float m = -1e30f;
        for (int i = tid; i < len; i += 256) m = fmaxf(m, sc[t][i]);
        #pragma unroll
        for (int o = 16; o > 0; o >>= 1) m = fmaxf(m, __shfl_xor_sync(0xffffffffu, m, o));
        if ((tid & 31) == 0) red[tid >> 5] = m;
        __syncthreads();
        m = fmaxf(fmaxf(fmaxf(red[0], red[1]), fmaxf(red[2], red[3])),
                  fmaxf(fmaxf(red[4], red[5]), fmaxf(red[6], red[7])));
        float ssum = 0.f;
        for (int i = tid; i < len; i += 256) {
            float e = __expf(sc[t][i] - m);
            sc[t][i] = e;
            ssum += e;
        }
        #pragma unroll
        for (int o = 16; o > 0; o >>= 1) ssum += __shfl_xor_sync(0xffffffffu, ssum, o);
        __syncthreads();
        if ((tid & 31) == 0) red[tid >> 5] = ssum;
        __syncthreads();
        if (tid == 0) {
            mt[t] = m;
            lt[t] = red[0]+red[1]+red[2]+red[3]+red[4]+red[5]+red[6]+red[7];
        }
        __syncthreads();
    }

    {
        int sg = tid >> 6, d = tid & 63;
        int q4 = (len + 3) >> 2;
        int i0 = sg * q4;
        int i1 = min(len, i0 + q4);
        const float* vp = vc + ((size_t)b * L + s0) * E + h * D + d;
        float a0 = 0.f, a1 = 0.f, a2 = 0.f, a3 = 0.f;
        int i = i0;
        for (; i + 2 <= i1; i += 2) {
            float v0 = vp[(size_t)i * E];
            float v1 = vp[(size_t)(i + 1) * E];
            a0 += sc[0][i] * v0 + sc[0][i+1] * v1;
            a1 += sc[1][i] * v0 + sc[1][i+1] * v1;
            a2 += sc[2][i] * v0 + sc[2][i+1] * v1;
            a3 += sc[3][i] * v0 + sc[3][i+1] * v1;
        }
        if (i < i1) {
            float v0 = vp[(size_t)i * E];
            a0 += sc[0][i] * v0;
            a1 += sc[1][i] * v0;
            a2 += sc[2][i] * v0;
            a3 += sc[3][i] * v0;
        }
        vpart[sg][0][d] = a0;
        vpart[sg][1][d] = a1;
        vpart[sg][2][d] = a2;
        vpart[sg][3][d] = a3;
    }
    __syncthreads();
    {
        int t = tid >> 6, d = tid & 63;
        float sum = vpart[0][t][d] + vpart[1][t][d] + vpart[2][t][d] + vpart[3][t][d];
        po[((size_t)(gbase + t)) * 64 + d] = sum;
        if (tid < 4) { gm[gbase + tid] = mt[tid]; gl[gbase + tid] = lt[tid]; }
    }
}

// -------- Attention combine --------
__global__ void attn_comb_kernel(const float* __restrict__ po,
                                 const float* __restrict__ gm,
                                 const float* __restrict__ gl,
                                 float* __restrict__ out)
{
    GDW();
    int bh = blockIdx.x;
    int b = bh >> 4, h = bh & 15;
    int tid = threadIdx.x;
    int t = tid >> 6, d = tid & 63;

    float m0 = gm[(bh * 4 + 0) * 4 + t];
    float m1 = gm[(bh * 4 + 1) * 4 + t];
    float m2 = gm[(bh * 4 + 2) * 4 + t];
    float m3 = gm[(bh * 4 + 3) * 4 + t];
    float M = fmaxf(fmaxf(m0, m1), fmaxf(m2, m3));
    float w0 = __expf(m0 - M), w1 = __expf(m1 - M);
    float w2 = __expf(m2 - M), w3 = __expf(m3 - M);
    float l = w0 * gl[(bh * 4 + 0) * 4 + t] + w1 * gl[(bh * 4 + 1) * 4 + t]
            + w2 * gl[(bh * 4 + 2) * 4 + t] + w3 * gl[(bh * 4 + 3) * 4 + t];
    float o = w0 * po[((size_t)(bh * 4 + 0) * 4 + t) * 64 + d]
            + w1 * po[((size_t)(bh * 4 + 1) * 4 + t) * 64 + d]
            + w2 * po[((size_t)(bh * 4 + 2) * 4 + t) * 64 + d]
            + w3 * po[((size_t)(bh * 4 + 3) * 4 + t) * 64 + d];
    out[((size_t)(b * T + t) * E) + h * D + d] = o / l;
}

// -------- host: PDL launch helper --------
template<typename F, typename... Args>
static inline void pdl(dim3 g, dim3 blk, F f, Args... args)
{
    cudaLaunchAttribute at[1];
    at[0].id = cudaLaunchAttributeProgrammaticStreamSerialization;
    at[0].val.programmaticStreamSerializationAllowed = 1;
    cudaLaunchConfig_t cfg = {};
    cfg.gridDim = g;
    cfg.blockDim = blk;
    cfg.dynamicSmemBytes = 0;
    cfg.stream = 0;
    cfg.attrs = at;
    cfg.numAttrs = 1;
    cudaLaunchKernelEx(&cfg, f, args...);
}

extern "C" void kernel_launch(void* const* d_in, const int* in_sizes, int n_in,
                              void* d_out, int out_size)
{
    const float* seq       = (const float*)d_in[0];
    const float* bos       = (const float*)d_in[1];
    const float* caches    = (const float*)d_in[2];
    const int*   positions = (const int*)  d_in[3];
    const float* in_w      = (const float*)d_in[4];
    const float* ip_w      = (const float*)d_in[5];
    const float* op_w      = (const float*)d_in[6];
    const float* n1w       = (const float*)d_in[7];
    const float* n1b       = (const float*)d_in[8];
    const float* n2w       = (const float*)d_in[9];
    const float* n2b       = (const float*)d_in[10];
    const float* l1_w      = (const float*)d_in[11];
    const float* l2_w      = (const float*)d_in[12];
    const float* on_w      = (const float*)d_in[13];
    const float* on_b      = (const float*)d_in[14];
    const float* eos_w     = (const float*)d_in[15];
    const float* eos_b     = (const float*)d_in[16];

    float* out = (float*)d_out;
    const size_t cache_elems = (size_t)NL * 2 * B * L * E;
    float* out_x     = out;
    float* out_eos   = out + (size_t)NTOK * E;
    float* out_cache = out_eos + NTOK;
    float* out_pos   = out_cache + cache_elems;

    float *px, *pxn, *pq, *pattn, *ph, *pseq, *ppart, *ppo, *pm, *pl;
    cudaGetSymbolAddress((void**)&px,    g_x);
    cudaGetSymbolAddress((void**)&pxn,   g_xn);
    cudaGetSymbolAddress((void**)&pq,    g_q);
    cudaGetSymbolAddress((void**)&pattn, g_attn);
    cudaGetSymbolAddress((void**)&ph,    g_h);
    cudaGetSymbolAddress((void**)&pseq,  g_seq);
    cudaGetSymbolAddress((void**)&ppart, g_part);
    cudaGetSymbolAddress((void**)&ppo,   g_po);
    cudaGetSymbolAddress((void**)&pm,    g_m);
    cudaGetSymbolAddress((void**)&pl,    g_l);

    long nf4 = (long)(cache_elems / 4);
    cache_copy_kernel<<<(unsigned)((nf4 + 255) / 256), 256>>>((const float4*)caches,
                                                              (float4*)out_cache, nf4);

    pdl(dim3(5), dim3(256), prep_pos_kernel, seq, bos, positions, pseq, out_pos);
    pdl(dim3(E / 64, 1), dim3(256), gemv_kernel<1>,
        (const float*)pseq, in_w, px, (float*)nullptr, (int)INDIM, (int)E);
    pdl(dim3(NTOK), dim3(256), ln_kernel, (const float*)px, n1w, n1b, pxn);

    for (int i = 0; i < NL; i++) {
        const float* ipw = ip_w + (size_t)i * 3 * E * E;
        const float* opw = op_w + (size_t)i * E * E;
        const float* l1  = l1_w + (size_t)i * FF * E;
        const float* l2  = l2_w + (size_t)i * E * FF;
        float* kcache = out_cache + ((size_t)i * 2 + 0) * B * L * E;
        float* vcache = out_cache + ((size_t)i * 2 + 1) * B * L * E;
        const int* posl = positions + i * B;

        // qkv: K=1024, N=3072, split-K=4 -> 192 blocks
        pdl(dim3(3 * E / 64, 4), dim3(256), gemv_kernel<4>,
            (const float*)pxn, ipw, (float*)nullptr, ppart, (int)E, (int)(3 * E));
        pdl(dim3(192), dim3(256), reduce_rope_kernel,
            (const float*)ppart, posl, pq, kcache, vcache);

        pdl(dim3(512), dim3(256), attn_part_kernel,
            (const float*)pq, (const float*)kcache, (const float*)vcache, posl,
            ppo, pm, pl);
        pdl(dim3(B * H), dim3(256), attn_comb_kernel,
            (const float*)ppo, (const float*)pm, (const float*)pl, pattn);

        // op: K=1024, N=1024, split-K=8 -> 128 blocks; fused reduce+add+LN
        pdl(dim3(E / 64, 8), dim3(256), gemv_kernel<8>,
            (const float*)pattn, opw, (float*)nullptr, ppart, (int)E, (int)E);
        pdl(dim3(NTOK), dim3(256), reduce_ln_kernel,
            (const float*)ppart, px, n2w + (size_t)i * E, n2b + (size_t)i * E, pxn);

        // l1: K=1024, N=4096, split-K=2 -> 128 blocks; gelu in reduce
        pdl(dim3(FF / 64, 2), dim3(256), gemv_kernel<2>,
            (const float*)pxn, l1, (float*)nullptr, ppart, (int)E, (int)FF);
        pdl(dim3((32 * FF + 255) / 256), dim3(256), reduce_gelu_kernel<2>,
            (const float*)ppart, ph, (int)FF);

        // l2: K=4096, N=1024, split-K=8 -> 128 blocks; fused reduce+add+LN/eos
        pdl(dim3(E / 64, 8), dim3(256), gemv_kernel<8>,
            (const float*)ph, l2, (float*)nullptr, ppart, (int)FF, (int)E);
        if (i + 1 < NL) {
            pdl(dim3(NTOK), dim3(256), reduce_ln_kernel,
                (const float*)ppart, px,
                n1w + (size_t)(i + 1) * E, n1b + (size_t)(i + 1) * E, pxn);
        } else {
            pdl(dim3(NTOK), dim3(256), reduce_ln_eos_kernel,
                (const float*)ppart, px, on_w, on_b, eos_w, eos_b,
                out_x, out_eos);
        }
    }
}

// round 15
// speedup vs baseline: 1.0854x; 1.0286x over previous
#include <cuda_runtime.h>
#include <math.h>

#define NL 6
#define B  8
#define T  4
#define L  2048
#define H  16
#define D  64
#define E  1024
#define FF 4096
#define INDIM 32
#define NTOK 32
#define DEPTH 3

#define CACHE_F4 50331648LL            // NL*2*B*L*E/4

#define GDW() asm volatile("griddepcontrol.wait;" ::: "memory")

// -------- scratch (device globals) --------
__device__ __align__(16) float g_x   [NTOK * E];
__device__ __align__(16) float g_xn  [NTOK * E];
__device__ __align__(16) float g_q   [NTOK * E];
__device__ __align__(16) float g_attn[NTOK * E];
__device__ __align__(16) float g_h   [NTOK * FF];
__device__ __align__(16) float g_seq [NTOK * INDIM];
__device__ __align__(16) float g_part[524288];

// -------- helpers --------
__device__ __forceinline__ unsigned long long pk2(float lo, float hi) {
    unsigned long long r;
    asm("mov.b64 %0, {%1, %2};" : "=l"(r) : "f"(lo), "f"(hi));
    return r;
}
__device__ __forceinline__ void fma2(unsigned long long& d,
                                     unsigned long long a,
                                     unsigned long long b) {
    asm("fma.rn.f32x2 %0, %1, %2, %3;" : "=l"(d) : "l"(a), "l"(b), "l"(d));
}
__device__ __forceinline__ float2 upk(unsigned long long v) {
    float2 f;
    asm("mov.b64 {%0, %1}, %2;" : "=f"(f.x), "=f"(f.y) : "l"(v));
    return f;
}
__device__ __forceinline__ void cpa16(unsigned dst, const void* src) {
    asm volatile("cp.async.ca.shared.global [%0], [%1], 16;" :: "r"(dst), "l"(src));
}
#define CP_COMMIT() asm volatile("cp.async.commit_group;")
#define CP_WAIT1()  asm volatile("cp.async.wait_group 1;")

// -------- bulk cache copy with NaN cleaning --------
__global__ void cache_copy_kernel(const float4* __restrict__ in,
                                  float4* __restrict__ out, long n)
{
    long i = (long)blockIdx.x * blockDim.x + threadIdx.x;
    if (i < n) {
        float4 v = in[i];
        v.x = isnan(v.x) ? 0.0f : v.x;
        v.y = isnan(v.y) ? 0.0f : v.y;
        v.z = isnan(v.z) ? 0.0f : v.z;
        v.w = isnan(v.w) ? 0.0f : v.w;
        out[i] = v;
    }
}

// -------- prep seq + new positions --------
__global__ void prep_pos_kernel(const float* __restrict__ seq,
                                const float* __restrict__ bos,
                                const int* __restrict__ positions,
                                float* __restrict__ out_seq,
                                float* __restrict__ out_pos)
{
    if (blockIdx.x < 4) {
        int i = blockIdx.x * 256 + threadIdx.x;
        float v = seq[i];
        out_seq[i] = isnan(v) ? bos[i & (INDIM - 1)] : v;
    } else {
        int i = threadIdx.x;
        if (i < NL * B) out_pos[i] = (float)(positions[i] + T);
    }
}

// ======== GEMM: Y[32,N] = X[32,K] @ W[N,K]^T ========
// W: cp.async 3-stage pipeline, prefetched BEFORE the PDL wait (W-only groups).
// X: float4 loads post-wait, 1-ahead prefetch, transposed-packed in smem.
// ONE barrier per chunk (second barrier provably unnecessary at DEPTH=3).
template<int KSPLIT>
__global__ void gemv_kernel(const float* __restrict__ X,
                            const float* __restrict__ W,
                            float* __restrict__ Y,
                            float* __restrict__ part,
                            int K, int N)
{
    __shared__ __align__(16) unsigned long long XsP[DEPTH][16][33];
    __shared__ __align__(16) float Ws[DEPTH][64][36];

    const int t    = threadIdx.x;
    const int lane = t & 31;
    const int c0   = (t >> 5) * 8;
    const int n0   = blockIdx.x * 64;
    const int Kc   = K / KSPLIT;
    const int kbase = blockIdx.y * Kc;
    const int nch  = Kc >> 5;

    const int xrow = t >> 3, xk4 = (t & 7) * 4;
    const int wrow = t >> 2, wk  = (t & 3) * 8;

    const float* xsrc = X + (size_t)xrow * K + kbase + xk4;
    const float* wsrc = W + (size_t)(n0 + wrow) * K + kbase + wk;

    const unsigned wbase = (unsigned)__cvta_generic_to_shared(&Ws[0][0][0])
                         + (unsigned)((wrow * 36 + wk) * 4);
    const unsigned WST = 64 * 36 * 4;

    // W prefetch stages 0..DEPTH-2 (launch-independent, pre-wait)
    #pragma unroll
    for (int p = 0; p < DEPTH - 1; p++) {
        if (p < nch) {
            cpa16(wbase + p * WST, wsrc + (size_t)p * 32);
            cpa16(wbase + p * WST + 16, wsrc + (size_t)p * 32 + 4);
        }
        CP_COMMIT();
    }
    GDW();   // predecessor output (X) now valid

    float4 xr = make_float4(0.f, 0.f, 0.f, 0.f);
    if (0 < nch) xr = *(const float4*)xsrc;

    unsigned long long acc[8];
    #pragma unroll
    for (int c = 0; c < 8; c++) acc[c] = 0ULL;

    int st = 0;
    int si = DEPTH - 1;
    for (int ch = 0; ch < nch; ch++) {
        CP_WAIT1();
        XsP[st][(xk4 >> 1)    ][xrow] = pk2(xr.x, xr.y);
        XsP[st][(xk4 >> 1) + 1][xrow] = pk2(xr.z, xr.w);
        __syncthreads();   // XsP[st] visible; bounds warp skew to 1 iteration

        if (ch + 1 < nch) xr = *(const float4*)(xsrc + (size_t)(ch + 1) * 32);

        #pragma unroll
        for (int p = 0; p < 16; p += 2) {
            unsigned long long x0 = XsP[st][p][lane];
            unsigned long long x1 = XsP[st][p + 1][lane];
            #pragma unroll
            for (int c = 0; c < 8; c++) {
                longlong2 w = *(const longlong2*)&Ws[st][c0 + c][2 * p];
                fma2(acc[c], x0, (unsigned long long)w.x);
                fma2(acc[c], x1, (unsigned long long)w.y);
            }
        }
        // no second barrier: writes target stage si (== st+2 mod 3) and the
        // next XsP write targets st+1; neither aliases the stage read above,
        // and the single barrier/iter bounds skew to one iteration.
        int nc = ch + DEPTH - 1;
        if (nc < nch) {
            cpa16(wbase + si * WST, wsrc + (size_t)nc * 32);
            cpa16(wbase + si * WST + 16, wsrc + (size_t)nc * 32 + 4);
        }
        CP_COMMIT();
        st = (st == DEPTH - 1) ? 0 : st + 1;
        si = (si == DEPTH - 1) ? 0 : si + 1;
    }

    if (KSPLIT == 1) {
        #pragma unroll
        for (int c = 0; c < 8; c++) {
            float2 p = upk(acc[c]);
            Y[(size_t)lane * N + n0 + c0 + c] = p.x + p.y;
        }
    } else {
        float* pp = part + ((size_t)blockIdx.y * 32 + lane) * N + n0 + c0;
        #pragma unroll
        for (int c = 0; c < 8; c++) {
            float2 p = upk(acc[c]);
            pp[c] = p.x + p.y;
        }
    }
}

// sum split-K partials + gelu (l1 path)
template<int KS>
__global__ void reduce_gelu_kernel(const float* __restrict__ part,
                                   float* __restrict__ Y, int N)
{
    GDW();
    int i = blockIdx.x * 256 + threadIdx.x;
    if (i >= 32 * N) return;
    int r = i / N, n = i - r * N;
    float s = 0.f;
    #pragma unroll
    for (int k = 0; k < KS; k++) s += part[((size_t)k * 32 + r) * N + n];
    Y[i] = 0.5f * s * (1.0f + erff(s * 0.70710678118654752f));
}

// -------- fused qkv split-K(4) reduce + RoPE + cache scatter --------
__global__ void reduce_rope_kernel(const float* __restrict__ part,
                                   const int* __restrict__ pos_l,
                                   float* __restrict__ qout,
                                   float* __restrict__ kcache,
                                   float* __restrict__ vcache)
{
    int id = blockIdx.x * 256 + threadIdx.x;
    int tok = id / 1536;
    int f   = (id - tok * 1536) * 2;
    int b = tok >> 2, t = tok & 3;
    int pos = pos_l[b];
    GDW();
    float s0 = 0.f, s1 = 0.f;
    #pragma unroll
    for (int k = 0; k < 4; k++) {
        const float* p = part + ((size_t)(k * 32 + tok) * 3072) + f;
        s0 += p[0];
        s1 += p[1];
    }
    if (f < E) {
        int j = (f & 63) >> 1;
        float freq = __expf(-(float)j * (logf(10000.0f) / 32.0f));
        float sn, cs;
        sincosf((float)(pos + t) * freq, &sn, &cs);
        qout[(size_t)tok * E + f]     = s0 * cs - s1 * sn;
        qout[(size_t)tok * E + f + 1] = s0 * sn + s1 * cs;
    } else if (f < 2 * E) {
        int fk = f - E;
        int j = (fk & 63) >> 1;
        float freq = __expf(-(float)j * (logf(10000.0f) / 32.0f));
        float sn, cs;
        sincosf((float)(pos + t) * freq, &sn, &cs);
        int slot = (pos + t) % L;
        size_t off = ((size_t)b * L + slot) * E + fk;
        kcache[off]     = s0 * cs - s1 * sn;
        kcache[off + 1] = s0 * sn + s1 * cs;
    } else {
        int fv = f - 2 * E;
        int slot = (pos + t) % L;
        size_t off = ((size_t)b * L + slot) * E + fv;
        vcache[off]     = s0;
        vcache[off + 1] = s1;
    }
}

// -------- LayerNorm (layer-0 entry) --------
__global__ void ln_kernel(const float* __restrict__ X,
                          const float* __restrict__ w,
                          const float* __restrict__ b,
                          float* __restrict__ Y)
{
    int tok = blockIdx.x;
    int tid = threadIdx.x;
    float wv[4], bv[4];
    #pragma unroll
    for (int j = 0; j < 4; j++) { wv[j] = w[tid + 256 * j]; bv[j] = b[tid + 256 * j]; }
    GDW();
    const float* x = X + (size_t)tok * E;
    float v[4];
    #pragma unroll
    for (int j = 0; j < 4; j++) v[j] = x[tid + 256 * j];
    float s = v[0] + v[1] + v[2] + v[3];
    #pragma unroll
    for (int o = 16; o > 0; o >>= 1) s += __shfl_xor_sync(0xffffffffu, s, o);
    __shared__ float ws[8];
    if ((tid & 31) == 0) ws[tid >> 5] = s;
    __syncthreads();
    float mean = (ws[0]+ws[1]+ws[2]+ws[3]+ws[4]+ws[5]+ws[6]+ws[7]) * (1.0f / E);
    float s2 = 0.f;
    #pragma unroll
    for (int j = 0; j < 4; j++) { float d = v[j] - mean; s2 += d * d; }
    #pragma unroll
    for (int o = 16; o > 0; o >>= 1) s2 += __shfl_xor_sync(0xffffffffu, s2, o);
    __syncthreads();
    if ((tid & 31) == 0) ws[tid >> 5] = s2;
    __syncthreads();
    float var = (ws[0]+ws[1]+ws[2]+ws[3]+ws[4]+ws[5]+ws[6]+ws[7]) * (1.0f / E);
    float r = rsqrtf(var + 1e-5f);
    #pragma unroll
    for (int j = 0; j < 4; j++) {
        int idx = tid + 256 * j;
        Y[(size_t)tok * E + idx] = (v[j] - mean) * r * wv[j] + bv[j];
    }
}

// -------- fused: x += sum(8 partials); xn = LN(x) --------
__global__ void reduce_ln_kernel(const float* __restrict__ part,
                                 float* __restrict__ x,
                                 const float* __restrict__ w,
                                 const float* __restrict__ b,
                                 float* __restrict__ xn)
{
    int tok = blockIdx.x;
    int tid = threadIdx.x;
    float wv[4], bv[4];
    #pragma unroll
    for (int j = 0; j < 4; j++) { wv[j] = w[tid + 256 * j]; bv[j] = b[tid + 256 * j]; }
    GDW();
    float v[4];
    #pragma unroll
    for (int j = 0; j < 4; j++) {
        int idx = tid + 256 * j;
        float p = 0.f;
        #pragma unroll
        for (int k = 0; k < 8; k++) p += part[((size_t)(k * 32 + tok)) * E + idx];
        float xv = x[(size_t)tok * E + idx] + p;
        x[(size_t)tok * E + idx] = xv;
        v[j] = xv;
    }
    float s = v[0] + v[1] + v[2] + v[3];
    #pragma unroll
    for (int o = 16; o > 0; o >>= 1) s += __shfl_xor_sync(0xffffffffu, s, o);
    __shared__ float ws[8];
    if ((tid & 31) == 0) ws[tid >> 5] = s;
    __syncthreads();
    float mean = (ws[0]+ws[1]+ws[2]+ws[3]+ws[4]+ws[5]+ws[6]+ws[7]) * (1.0f / E);
    float s2 = 0.f;
    #pragma unroll
    for (int j = 0; j < 4; j++) { float d = v[j] - mean; s2 += d * d; }
    #pragma unroll
    for (int o = 16; o > 0; o >>= 1) s2 += __shfl_xor_sync(0xffffffffu, s2, o);
    __syncthreads();
    if ((tid & 31) == 0) ws[tid >> 5] = s2;
    __syncthreads();
    float var = (ws[0]+ws[1]+ws[2]+ws[3]+ws[4]+ws[5]+ws[6]+ws[7]) * (1.0f / E);
    float r = rsqrtf(var + 1e-5f);
    #pragma unroll
    for (int j = 0; j < 4; j++) {
        int idx = tid + 256 * j;
        xn[(size_t)tok * E + idx] = (v[j] - mean) * r * wv[j] + bv[j];
    }
}

// -------- fused: x += partials; out_x = LN(x); eos dot --------
__global__ void reduce_ln_eos_kernel(const float* __restrict__ part,
                                     float* __restrict__ x,
                                     const float* __restrict__ w,
                                     const float* __restrict__ b,
                                     const float* __restrict__ ew,
                                     const float* __restrict__ eb,
                                     float* __restrict__ Y,
                                     float* __restrict__ out_eos)
{
    int tok = blockIdx.x;
    int tid = threadIdx.x;
    float wv[4], bv[4], ev[4];
    #pragma unroll
    for (int j = 0; j < 4; j++) {
        wv[j] = w[tid + 256 * j];
        bv[j] = b[tid + 256 * j];
        ev[j] = ew[tid + 256 * j];
    }
    GDW();
    float v[4];
    #pragma unroll
    for (int j = 0; j < 4; j++) {
        int idx = tid + 256 * j;
        float p = 0.f;
        #pragma unroll
        for (int k = 0; k < 8; k++) p += part[((size_t)(k * 32 + tok)) * E + idx];
        v[j] = x[(size_t)tok * E + idx] + p;
    }
    float s = v[0] + v[1] + v[2] + v[3];
    #pragma unroll
    for (int o = 16; o > 0; o >>= 1) s += __shfl_xor_sync(0xffffffffu, s, o);
    __shared__ float ws[8];
    if ((tid & 31) == 0) ws[tid >> 5] = s;
    __syncthreads();
    float mean = (ws[0]+ws[1]+ws[2]+ws[3]+ws[4]+ws[5]+ws[6]+ws[7]) * (1.0f / E);
    float s2 = 0.f;
    #pragma unroll
    for (int j = 0; j < 4; j++) { float d = v[j] - mean; s2 += d * d; }
    #pragma unroll
    for (int o = 16; o > 0; o >>= 1) s2 += __shfl_xor_sync(0xffffffffu, s2, o);
    __syncthreads();
    if ((tid & 31) == 0) ws[tid >> 5] = s2;
    __syncthreads();
    float var = (ws[0]+ws[1]+ws[2]+ws[3]+ws[4]+ws[5]+ws[6]+ws[7]) * (1.0f / E);
    float r = rsqrtf(var + 1e-5f);
    float ed = 0.f;
    #pragma unroll
    for (int j = 0; j < 4; j++) {
        int idx = tid + 256 * j;
        float y = (v[j] - mean) * r * wv[j] + bv[j];
        Y[(size_t)tok * E + idx] = y;
        ed += y * ev[j];
    }
    #pragma unroll
    for (int o = 16; o > 0; o >>= 1) ed += __shfl_xor_sync(0xffffffffu, ed, o);
    __syncthreads();
    if ((tid & 31) == 0) ws[tid >> 5] = ed;
    __syncthreads();
    if (tid == 0)
        out_eos[tok] = ws[0]+ws[1]+ws[2]+ws[3]+ws[4]+ws[5]+ws[6]+ws[7] + eb[0];
}

// -------- Attention: ONE kernel, one block per (b,h), 256 threads --------
#define SMAX 1056
__global__ void attn_kernel(const float* __restrict__ q,
                            const float* __restrict__ kc,
                            const float* __restrict__ vc,
                            const int* __restrict__ pos_l,
                            float* __restrict__ out)
{
    __shared__ float qs[4][64];
    __shared__ float sc[4][SMAX];
    __shared__ float red[8];
    __shared__ float inv[4];
    __shared__ float vpart[4][4][64];

    int bh = blockIdx.x;
    int b = bh >> 4, h = bh & 15;
    int tid = threadIdx.x;
    int pos = pos_l[b];
    GDW();
    int slen = pos + T;

    {
        int t = tid >> 6, d = tid & 63;
        qs[t][d] = q[((size_t)(b * T + t) * E) + h * D + d];
    }
    __syncthreads();

    const float scale = 0.125f;
    for (int s = tid; s < slen; s += 256) {
        const float4* kr = (const float4*)(kc + ((size_t)b * L + s) * E + h * D);
        float d0 = 0.f, d1 = 0.f, d2 = 0.f, d3 = 0.f;
        #pragma unroll
        for (int i4 = 0; i4 < 16; i4++) {
            float4 kv = kr[i4];
            int d = i4 * 4;
            d0 += qs[0][d]*kv.x + qs[0][d+1]*kv.y + qs[0][d+2]*kv.z + qs[0][d+3]*kv.w;
            d1 += qs[1][d]*kv.x + qs[1][d+1]*kv.y + qs[1][d+2]*kv.z + qs[1][d+3]*kv.w;
            d2 += qs[2][d]*kv.x + qs[2][d+1]*kv.y + qs[2][d+2]*kv.z + qs[2][d+3]*kv.w;
            d3 += qs[3][d]*kv.x + qs[3][d+1]*kv.y + qs[3][d+2]*kv.z + qs[3][d+3]*kv.w;
        }
        sc[0][s] = (s <= pos + 0) ? d0 * scale : -1e30f;
        sc[1][s] = (s <= pos + 1) ? d1 * scale : -1e30f;
        sc[2][s] = (s <= pos + 2) ? d2 * scale : -1e30f;
        sc[3][s] = (s <= pos + 3) ? d3 * scale : -1e30f;
    }
    __syncthreads();

    #pragma unroll
    for (int t = 0; t < 4; t++) {
        float m = -1e30f;
        for (int s = tid; s < slen; s += 256) m = fmaxf(m, sc[t][s]);
        #pragma unroll
        for (int o = 16; o > 0; o >>= 1) m = fmaxf(m, __shfl_xor_sync(0xffffffffu, m, o));
        if ((tid & 31) == 0) red[tid >> 5] = m;
        __syncthreads();
        m = fmaxf(fmaxf(fmaxf(red[0], red[1]), fmaxf(red[2], red[3])),
                  fmaxf(fmaxf(red[4], red[5]), fmaxf(red[6], red[7])));
        float ssum = 0.f;
        for (int s = tid; s < slen; s += 256) {
            float e = __expf(sc[t][s] - m);
            sc[t][s] = e;
            ssum += e;
        }
        #pragma unroll
        for (int o = 16; o > 0; o >>= 1) ssum += __shfl_xor_sync(0xffffffffu, ssum, o);
        __syncthreads();
        if ((tid & 31) == 0) red[tid >> 5] = ssum;
        __syncthreads();
        if (tid == 0)
            inv[t] = 1.0f / (red[0]+red[1]+red[2]+red[3]+red[4]+red[5]+red[6]+red[7]);
        __syncthreads();
    }

    {
        int sg = tid >> 6, d = tid & 63;
        int chunk = (slen + 3) >> 2;
        int s0 = sg * chunk;
        int s1 = min(slen, s0 + chunk);
        const float* vp = vc + (size_t)b * L * E + h * D + d;
        float a0 = 0.f, a1 = 0.f, a2 = 0.f, a3 = 0.f;
        int s = s0;
        for (; s + 2 <= s1; s += 2) {
            float v0 = vp[(size_t)s * E];
            float v1 = vp[(size_t)(s + 1) * E];
            a0 += sc[0][s] * v0 + sc[0][s+1] * v1;
            a1 += sc[1][s] * v0 + sc[1][s+1] * v1;
            a2 += sc[2][s] * v0 + sc[2][s+1] * v1;
            a3 += sc[3][s] * v0 + sc[3][s+1] * v1;
        }
        if (s < s1) {
            float v0 = vp[(size_t)s * E];
            a0 += sc[0][s] * v0;
            a1 += sc[1][s] * v0;
            a2 += sc[2][s] * v0;
            a3 += sc[3][s] * v0;
        }
        vpart[sg][0][d] = a0;
        vpart[sg][1][d] = a1;
        vpart[sg][2][d] = a2;
        vpart[sg][3][d] = a3;
    }
    __syncthreads();
    {
        int t = tid >> 6, d = tid & 63;
        float sum = vpart[0][t][d] + vpart[1][t][d] + vpart[2][t][d] + vpart[3][t][d];
        out[((size_t)(b * T + t) * E) + h * D + d] = sum * inv[t];
    }
}

// -------- host: PDL launch helper --------
template<typename F, typename... Args>
static inline void pdl(dim3 g, dim3 blk, F f, Args... args)
{
    cudaLaunchAttribute at[1];
    at[0].id = cudaLaunchAttributeProgrammaticStreamSerialization;
    at[0].val.programmaticStreamSerializationAllowed = 1;
    cudaLaunchConfig_t cfg = {};
    cfg.gridDim = g;
    cfg.blockDim = blk;
    cfg.dynamicSmemBytes = 0;
    cfg.stream = 0;
    cfg.attrs = at;
    cfg.numAttrs = 1;
    cudaLaunchKernelEx(&cfg, f, args...);
}

extern "C" void kernel_launch(void* const* d_in, const int* in_sizes, int n_in,
                              void* d_out, int out_size)
{
    const float* seq       = (const float*)d_in[0];
    const float* bos       = (const float*)d_in[1];
    const float* caches    = (const float*)d_in[2];
    const int*   positions = (const int*)  d_in[3];
    const float* in_w      = (const float*)d_in[4];
    const float* ip_w      = (const float*)d_in[5];
    const float* op_w      = (const float*)d_in[6];
    const float* n1w       = (const float*)d_in[7];
    const float* n1b       = (const float*)d_in[8];
    const float* n2w       = (const float*)d_in[9];
    const float* n2b       = (const float*)d_in[10];
    const float* l1_w      = (const float*)d_in[11];
    const float* l2_w      = (const float*)d_in[12];
    const float* on_w      = (const float*)d_in[13];
    const float* on_b      = (const float*)d_in[14];
    const float* eos_w     = (const float*)d_in[15];
    const float* eos_b     = (const float*)d_in[16];

    float* out = (float*)d_out;
    const size_t cache_elems = (size_t)NL * 2 * B * L * E;
    float* out_x     = out;
    float* out_eos   = out + (size_t)NTOK * E;
    float* out_cache = out_eos + NTOK;
    float* out_pos   = out_cache + cache_elems;

    float *px, *pxn, *pq, *pattn, *ph, *pseq, *ppart;
    cudaGetSymbolAddress((void**)&px,    g_x);
    cudaGetSymbolAddress((void**)&pxn,   g_xn);
    cudaGetSymbolAddress((void**)&pq,    g_q);
    cudaGetSymbolAddress((void**)&pattn, g_attn);
    cudaGetSymbolAddress((void**)&ph,    g_h);
    cudaGetSymbolAddress((void**)&pseq,  g_seq);
    cudaGetSymbolAddress((void**)&ppart, g_part);

    long nf4 = (long)(cache_elems / 4);
    cache_copy_kernel<<<(unsigned)((nf4 + 255) / 256), 256>>>((const float4*)caches,
                                                              (float4*)out_cache, nf4);

    pdl(dim3(5), dim3(256), prep_pos_kernel, seq, bos, positions, pseq, out_pos);
    pdl(dim3(E / 64, 1), dim3(256), gemv_kernel<1>,
        (const float*)pseq, in_w, px, (float*)nullptr, (int)INDIM, (int)E);
    pdl(dim3(NTOK), dim3(256), ln_kernel, (const float*)px, n1w, n1b, pxn);

    for (int i = 0; i < NL; i++) {
        const float* ipw = ip_w + (size_t)i * 3 * E * E;
        const float* opw = op_w + (size_t)i * E * E;
        const float* l1  = l1_w + (size_t)i * FF * E;
        const float* l2  = l2_w + (size_t)i * E * FF;
        float* kcache = out_cache + ((size_t)i * 2 + 0) * B * L * E;
        float* vcache = out_cache + ((size_t)i * 2 + 1) * B * L * E;
        const int* posl = positions + i * B;

        // qkv: K=1024, N=3072, split-K=4 -> 192 blocks
        pdl(dim3(3 * E / 64, 4), dim3(256), gemv_kernel<4>,
            (const float*)pxn, ipw, (float*)nullptr, ppart, (int)E, (int)(3 * E));
        pdl(dim3(192), dim3(256), reduce_rope_kernel,
            (const float*)ppart, posl, pq, kcache, vcache);

        // attention: single kernel, one block per (b,h)
        pdl(dim3(B * H), dim3(256), attn_kernel,
            (const float*)pq, (const float*)kcache, (const float*)vcache, posl,
            pattn);

        // op: K=1024, N=1024, split-K=8 -> 128 blocks; fused reduce+add+LN
        pdl(dim3(E / 64, 8), dim3(256), gemv_kernel<8>,
            (const float*)pattn, opw, (float*)nullptr, ppart, (int)E, (int)E);
        pdl(dim3(NTOK), dim3(256), reduce_ln_kernel,
            (const float*)ppart, px, n2w + (size_t)i * E, n2b + (size_t)i * E, pxn);

        // l1: K=1024, N=4096, split-K=2 -> 128 blocks; gelu in reduce
        pdl(dim3(FF / 64, 2), dim3(256), gemv_kernel<2>,
            (const float*)pxn, l1, (float*)nullptr, ppart, (int)E, (int)FF);
        pdl(dim3((32 * FF + 255) / 256), dim3(256), reduce_gelu_kernel<2>,
            (const float*)ppart, ph, (int)FF);

        // l2: K=4096, N=1024, split-K=8 -> 128 blocks; fused reduce+add+LN/eos
        pdl(dim3(E / 64, 8), dim3(256), gemv_kernel<8>,
            (const float*)ph, l2, (float*)nullptr, ppart, (int)FF, (int)E);
        if (i + 1 < NL) {
            pdl(dim3(NTOK), dim3(256), reduce_ln_kernel,
                (const float*)ppart, px,
                n1w + (size_t)(i + 1) * E, n1b + (size_t)(i + 1) * E, pxn);
        } else {
            pdl(dim3(NTOK), dim3(256), reduce_ln_eos_kernel,
                (const float*)ppart, px, on_w, on_b, eos_w, eos_b,
                out_x, out_eos);
        }
    }
}